// round 3
// baseline (speedup 1.0000x reference)
#include <cuda_runtime.h>
#include <math.h>

// ---------------- scratch (device globals, no allocation) ----------------
__device__ float g_feats[8192 * 8];
__device__ float g_Ur[256 * 256];
__device__ float g_Ui[256 * 256];
__device__ float g_M[256 * 256];
__device__ float g_T[6561];
__device__ float2 g_G[17][16];   // fused 4x4 gates

// ---------------- complex helpers ----------------
__device__ __forceinline__ float2 cmul(float2 a, float2 b) {
    return make_float2(a.x * b.x - a.y * b.y, a.x * b.y + a.y * b.x);
}
__device__ __forceinline__ float2 cadd(float2 a, float2 b) {
    return make_float2(a.x + b.x, a.y + b.y);
}

// Pauli matrices I,X,Y,Z
__constant__ float2 c_P[4][2][2] = {
    { { {1.f,0.f},{0.f,0.f} }, { {0.f,0.f},{1.f,0.f} } },   // I
    { { {0.f,0.f},{1.f,0.f} }, { {1.f,0.f},{0.f,0.f} } },   // X
    { { {0.f,0.f},{0.f,-1.f} }, { {0.f,1.f},{0.f,0.f} } },  // Y
    { { {1.f,0.f},{0.f,0.f} }, { {0.f,0.f},{-1.f,0.f} } },  // Z
};

// wires (wa, wb) for the 17 fused gates
__constant__ int c_gwa[17] = {0,2,4,6,1,3,5, 1,3,5,7, 0,4,2, 2,6, 0};
__constant__ int c_gwb[17] = {1,3,5,7,2,4,6, 0,2,4,6, 2,6,4, 0,4, 4};

// ---------------- K1: feats = tanh(x @ fc_w^T + fc_b) ----------------
__global__ __launch_bounds__(256) void feats_kernel(const float* __restrict__ x,
                                                    const float* __restrict__ fcw,
                                                    const float* __restrict__ fcb) {
    extern __shared__ float wsh[];  // 8*3072 floats = 96KB
    int tid = threadIdx.x;
    for (int i = tid * 4; i < 8 * 3072; i += 256 * 4)
        *(float4*)&wsh[i] = *(const float4*)&fcw[i];
    __syncthreads();

    int warp = tid >> 5, lane = tid & 31;
    int grp = blockIdx.x * 8 + warp;
    long long row0 = (long long)grp * 4;

    float acc[8][4];
#pragma unroll
    for (int q = 0; q < 8; q++)
#pragma unroll
        for (int r = 0; r < 4; r++) acc[q][r] = 0.f;

#pragma unroll 4
    for (int it = 0; it < 24; it++) {
        int c = (it * 32 + lane) * 4;
        float4 xv[4];
#pragma unroll
        for (int r = 0; r < 4; r++)
            xv[r] = *(const float4*)&x[(row0 + r) * 3072 + c];
#pragma unroll
        for (int q = 0; q < 8; q++) {
            float4 wv = *(const float4*)&wsh[q * 3072 + c];
#pragma unroll
            for (int r = 0; r < 4; r++) {
                acc[q][r] += wv.x * xv[r].x + wv.y * xv[r].y +
                             wv.z * xv[r].z + wv.w * xv[r].w;
            }
        }
    }
#pragma unroll
    for (int q = 0; q < 8; q++) {
#pragma unroll
        for (int r = 0; r < 4; r++) {
            float v = acc[q][r];
            v += __shfl_down_sync(0xffffffffu, v, 16);
            v += __shfl_down_sync(0xffffffffu, v, 8);
            v += __shfl_down_sync(0xffffffffu, v, 4);
            v += __shfl_down_sync(0xffffffffu, v, 2);
            v += __shfl_down_sync(0xffffffffu, v, 1);
            if (lane == 0) g_feats[(row0 + r) * 8 + q] = tanhf(v + fcb[q]);
        }
    }
}

// ---------------- gate construction ----------------
__device__ __forceinline__ void u3g(float th, float ph, float dl, float2 g[2][2]) {
    float st, ct; __sincosf(0.5f * th, &st, &ct);
    float sp, cp; __sincosf(ph, &sp, &cp);
    float sd, cd; __sincosf(dl, &sd, &cd);
    float spd, cpd; __sincosf(ph + dl, &spd, &cpd);
    g[0][0] = make_float2(ct, 0.f);
    g[0][1] = make_float2(-cd * st, -sd * st);
    g[1][0] = make_float2(cp * st, sp * st);
    g[1][1] = make_float2(cpd * ct, spd * ct);
}

__device__ __forceinline__ void zero4(float2 g[4][4]) {
#pragma unroll
    for (int r = 0; r < 4; r++)
#pragma unroll
        for (int c = 0; c < 4; c++) g[r][c] = make_float2(0.f, 0.f);
}

__device__ __forceinline__ void kron22(const float2 A[2][2], const float2 B[2][2],
                                       float2 P[4][4]) {
#pragma unroll
    for (int ra = 0; ra < 2; ra++)
#pragma unroll
        for (int rb = 0; rb < 2; rb++)
#pragma unroll
            for (int ca = 0; ca < 2; ca++)
#pragma unroll
                for (int cb = 0; cb < 2; cb++)
                    P[ra * 2 + rb][ca * 2 + cb] = cmul(A[ra][ca], B[rb][cb]);
}

__device__ __forceinline__ void mm4(const float2 A[4][4], const float2 B[4][4],
                                    float2 C[4][4]) {
#pragma unroll
    for (int i = 0; i < 4; i++)
#pragma unroll
        for (int j = 0; j < 4; j++) {
            float2 s = make_float2(0.f, 0.f);
#pragma unroll
            for (int k = 0; k < 4; k++) s = cadd(s, cmul(A[i][k], B[k][j]));
            C[i][j] = s;
        }
}

// one small block: precompute the 17 fused 4x4 gate matrices
__global__ __launch_bounds__(32) void gates_kernel(const float* __restrict__ conv,
                                                   const float* __restrict__ pool,
                                                   const float* __restrict__ last) {
    int g = threadIdx.x;
    if (g >= 17) return;
    float2 G[4][4];

    bool is_conv = (g <= 6) || (g >= 11 && g <= 13);
    bool is_pool = (g >= 7 && g <= 10) || (g == 14) || (g == 15);

    if (is_conv) {
        int layer, idx;
        if (g <= 6) { const int ii[7] = {0, 2, 4, 6, 1, 3, 5}; layer = 0; idx = ii[g]; }
        else        { const int ii[3] = {0, 2, 1};             layer = 1; idx = ii[g - 11]; }
        const float* cw = conv + layer * 8 * 15;
        float2 A1[2][2], B1[2][2], A2[2][2], B2[2][2];
        u3g(cw[idx * 15 + 0], cw[idx * 15 + 1], cw[idx * 15 + 2], A1);
        u3g(cw[(idx + 1) * 15 + 3], cw[(idx + 1) * 15 + 4], cw[(idx + 1) * 15 + 5], B1);
        u3g(cw[idx * 15 + 9], cw[idx * 15 + 10], cw[idx * 15 + 11], A2);
        u3g(cw[(idx + 1) * 15 + 12], cw[(idx + 1) * 15 + 13], cw[(idx + 1) * 15 + 14], B2);
        float2 P1[4][4], P2[4][4], T1[4][4], T2[4][4], IS[4][4];
        kron22(A1, B1, P1);
        kron22(A2, B2, P2);
        // ZZ
        {
            float sn, cs; __sincosf(0.5f * cw[idx * 15 + 6], &sn, &cs);
            zero4(IS);
            IS[0][0] = make_float2(cs, -sn);
            IS[1][1] = make_float2(cs, sn);
            IS[2][2] = make_float2(cs, sn);
            IS[3][3] = make_float2(cs, -sn);
            mm4(IS, P1, T1);
        }
        // YY
        {
            float sn, cs; __sincosf(0.5f * cw[idx * 15 + 7], &sn, &cs);
            zero4(IS);
            IS[0][0] = IS[1][1] = IS[2][2] = IS[3][3] = make_float2(cs, 0.f);
            IS[0][3] = make_float2(0.f, sn);
            IS[1][2] = make_float2(0.f, -sn);
            IS[2][1] = make_float2(0.f, -sn);
            IS[3][0] = make_float2(0.f, sn);
            mm4(IS, T1, T2);
        }
        // XX
        {
            float sn, cs; __sincosf(0.5f * cw[idx * 15 + 8], &sn, &cs);
            zero4(IS);
            IS[0][0] = IS[1][1] = IS[2][2] = IS[3][3] = make_float2(cs, 0.f);
            IS[0][3] = IS[1][2] = IS[2][1] = IS[3][0] = make_float2(0.f, -sn);
            mm4(IS, T2, T1);
        }
        mm4(P2, T1, G);
    } else if (is_pool) {
        int layer = (g <= 10) ? 0 : 1;
        int pi = (g <= 10) ? (g - 7) : (g - 14);
        const float* pw = pool + layer * 4 * 3;
        float2 u[2][2];
        u3g(pw[pi * 3 + 0], pw[pi * 3 + 1], pw[pi * 3 + 2], u);
        zero4(G);
        G[0][0] = make_float2(1.f, 0.f);
        G[1][1] = make_float2(1.f, 0.f);
        G[2][2] = u[0][0]; G[2][3] = u[0][1];
        G[3][2] = u[1][0]; G[3][3] = u[1][1];
    } else {
        // g == 16: product of the 15 Pauli-word rotations
        zero4(G);
#pragma unroll
        for (int i = 0; i < 4; i++) G[i][i] = make_float2(1.f, 0.f);
        for (int kk = 0; kk < 15; kk++) {
            int pa = (kk + 1) >> 2, pb = (kk + 1) & 3;
            float sn, cs; __sincosf(0.5f * last[kk], &sn, &cs);
            float2 Mk[4][4], T1[4][4];
#pragma unroll
            for (int r = 0; r < 4; r++)
#pragma unroll
                for (int c = 0; c < 4; c++) {
                    float2 p2 = cmul(c_P[pa][r >> 1][c >> 1], c_P[pb][r & 1][c & 1]);
                    Mk[r][c] = make_float2((r == c ? cs : 0.f) + sn * p2.y, -sn * p2.x);
                }
            mm4(Mk, G, T1);
#pragma unroll
            for (int r = 0; r < 4; r++)
#pragma unroll
                for (int c = 0; c < 4; c++) G[r][c] = T1[r][c];
        }
    }
#pragma unroll
    for (int r = 0; r < 4; r++)
#pragma unroll
        for (int c = 0; c < 4; c++) g_G[g][r * 4 + c] = G[r][c];
}

// ---------------- K2: apply 17 fused gates to basis columns ----------------
__device__ __forceinline__ void apply2(float2* s, const float2 g[4][4], int wa, int wb, int t) {
    __syncthreads();
    int ma = 1 << (7 - wa), mb = 1 << (7 - wb);
    int lo = ma < mb ? ma : mb;
    int hi = ma < mb ? mb : ma;
    int k = t;
    k = ((k & ~(lo - 1)) << 1) | (k & (lo - 1));
    k = ((k & ~(hi - 1)) << 1) | (k & (hi - 1));
    int i0 = k, i1 = k | mb, i2 = k | ma, i3 = k | ma | mb;
    float2 v0 = s[i0], v1 = s[i1], v2 = s[i2], v3 = s[i3];
    float2 o0 = cadd(cadd(cmul(g[0][0], v0), cmul(g[0][1], v1)),
                     cadd(cmul(g[0][2], v2), cmul(g[0][3], v3)));
    float2 o1 = cadd(cadd(cmul(g[1][0], v0), cmul(g[1][1], v1)),
                     cadd(cmul(g[1][2], v2), cmul(g[1][3], v3)));
    float2 o2 = cadd(cadd(cmul(g[2][0], v0), cmul(g[2][1], v1)),
                     cadd(cmul(g[2][2], v2), cmul(g[2][3], v3)));
    float2 o3 = cadd(cadd(cmul(g[3][0], v0), cmul(g[3][1], v1)),
                     cadd(cmul(g[3][2], v2), cmul(g[3][3], v3)));
    s[i0] = o0; s[i1] = o1; s[i2] = o2; s[i3] = o3;
}

__global__ __launch_bounds__(64) void circuit_kernel() {
    __shared__ float2 s[256];
    int t = threadIdx.x;
    int col = blockIdx.x;
    for (int k = t; k < 256; k += 64)
        s[k] = make_float2(k == col ? 1.f : 0.f, 0.f);

    for (int g = 0; g < 17; g++) {
        float2 g4[4][4];
        const float2* Gp = &g_G[g][0];
#pragma unroll
        for (int r = 0; r < 4; r++)
#pragma unroll
            for (int c = 0; c < 4; c++) g4[r][c] = Gp[r * 4 + c];
        apply2(s, g4, c_gwa[g], c_gwb[g], t);
    }
    __syncthreads();
    for (int k = t; k < 256; k += 64) {
        g_Ur[k * 256 + col] = s[k].x;
        g_Ui[k * 256 + col] = s[k].y;
    }
}

// ---------------- K3: M = Ur^T diag(z) Ur + Ui^T diag(z) Ui ----------------
__global__ __launch_bounds__(256) void msyrk_kernel() {
    int bi = blockIdx.y * 16, bj = blockIdx.x * 16;
    int tx = threadIdx.x & 15, ty = threadIdx.x >> 4;
    __shared__ float Air[16][17], Aii[16][17], Ajr[16][17], Aji[16][17];
    float acc = 0.f;
    for (int k0 = 0; k0 < 256; k0 += 16) {
        int k = k0 + ty;
        float z = (k & 128) ? -1.f : 1.f;  // wire 0 is the MSB
        Air[ty][tx] = z * g_Ur[k * 256 + bi + tx];
        Aii[ty][tx] = z * g_Ui[k * 256 + bi + tx];
        Ajr[ty][tx] = g_Ur[k * 256 + bj + tx];
        Aji[ty][tx] = g_Ui[k * 256 + bj + tx];
        __syncthreads();
#pragma unroll
        for (int kkk = 0; kkk < 16; kkk++)
            acc += Air[kkk][ty] * Ajr[kkk][tx] + Aii[kkk][ty] * Aji[kkk][tx];
        __syncthreads();
    }
    g_M[(bi + ty) * 256 + bj + tx] = acc;
}

// ---------------- K4: M -> T, single block, digit-separable ----------------
__global__ __launch_bounds__(1024) void pauli_kernel() {
    extern __shared__ float S[];  // 49152 floats = 192KB
    unsigned t = threadIdx.x;

    // stage 0: contract digit 0 (bit 7 of row/col) from g_M -> S[3][128][128]
#pragma unroll
    for (int u = 0; u < 48; u++) {
        unsigned o = t + u * 1024u;
        unsigned p = o >> 14, rem = o & 16383u, i = rem >> 7, j = rem & 127u;
        float v;
        if (p == 0)      v = g_M[i * 256 + j] + g_M[(i + 128) * 256 + j + 128];
        else if (p == 1) v = g_M[i * 256 + j] - g_M[(i + 128) * 256 + j + 128];
        else             v = g_M[i * 256 + j + 128] + g_M[(i + 128) * 256 + j];
        S[o] = v;
    }
    __syncthreads();

    unsigned nc = 3;
    for (int st = 1; st < 8; st++) {
        unsigned sh = 7 - st;              // log2(half)
        unsigned half = 1u << sh;
        unsigned hh = half * half;
        unsigned n_out = nc * 3 * hh;
        unsigned in_blk = 4 * hh;
        unsigned full = half << 1;
        float reg[36];
#pragma unroll
        for (int u = 0; u < 36; u++) {
            unsigned o = t + (u << 10);
            if (o < n_out) {
                unsigned j = o & (half - 1);
                unsigned r1 = o >> sh;
                unsigned i = r1 & (half - 1);
                unsigned r2 = r1 >> sh;
                unsigned p = r2 % 3u;
                unsigned c = r2 / 3u;
                const float* base = S + c * in_blk;
                float v;
                if (p == 0)      v = base[i * full + j] + base[(i + half) * full + j + half];
                else if (p == 1) v = base[i * full + j] - base[(i + half) * full + j + half];
                else             v = base[i * full + j + half] + base[(i + half) * full + j];
                reg[u] = v;
            }
        }
        __syncthreads();
#pragma unroll
        for (int u = 0; u < 36; u++) {
            unsigned o = t + (u << 10);
            if (o < n_out) S[o] = reg[u];
        }
        __syncthreads();
        nc *= 3;
    }
    for (unsigned o = t; o < 6561; o += 1024) g_T[o] = S[o];
}

// ---------------- K5: qval = a^T T b / 256; logits ----------------
__device__ __forceinline__ float selt(int d, float c, float s) {
    return d == 0 ? 1.f : (d == 1 ? c : s);
}

__global__ __launch_bounds__(256) void logits_kernel(const float* __restrict__ out_w,
                                                     const float* __restrict__ out_b,
                                                     float* __restrict__ out) {
    extern __shared__ float sm[];
    float* Tsh = sm;                 // 81*84  = 6804
    float* ash = Tsh + 81 * 84;      // 64*84  = 5376
    float* bsh = ash + 64 * 84;      // 64*84  = 5376
    float* qps = bsh + 64 * 84;      // 64*16  = 1024
    float* qvs = qps + 64 * 16;      // 64

    int t = threadIdx.x;
    for (int i = t; i < 81 * 84; i += 256) Tsh[i] = 0.f;
    for (int i = t; i < 64 * 84; i += 256) bsh[i] = 0.f;
    __syncthreads();
    for (int i = t; i < 6561; i += 256) Tsh[(i / 81) * 84 + (i % 81)] = g_T[i];

    // per-sample a (wires 0-3) and b (wires 4-7) factors: 4 threads per sample
    {
        int s = t >> 2, part = t & 3;
        int sg = blockIdx.x * 64 + s;
        float tc[8], ts[8];
#pragma unroll
        for (int w = 0; w < 8; w++) {
            float f = g_feats[sg * 8 + w];
            __sincosf(f, &ts[w], &tc[w]);
        }
        int m0 = part * 21;
        int m1 = m0 + 21; if (m1 > 81) m1 = 81;
        for (int m = m0; m < m1; m++) {
            int d0 = m / 27, d1 = (m / 9) % 3, d2 = (m / 3) % 3, d3 = m % 3;
            ash[s * 84 + m] = selt(d0, tc[0], ts[0]) * selt(d1, tc[1], ts[1]) *
                              selt(d2, tc[2], ts[2]) * selt(d3, tc[3], ts[3]);
            bsh[s * 84 + m] = selt(d0, tc[4], ts[4]) * selt(d1, tc[5], ts[5]) *
                              selt(d2, tc[6], ts[6]) * selt(d3, tc[7], ts[7]);
        }
    }
    __syncthreads();

    // register-tiled bilinear: thread handles 4 samples x 6 n's
    if (t < 224) {
        int sg = t / 14, ng = t % 14;
        int s0 = sg * 4, n0 = ng * 6;
        float e[4][6];
#pragma unroll
        for (int i = 0; i < 4; i++)
#pragma unroll
            for (int j = 0; j < 6; j++) e[i][j] = 0.f;
        for (int m = 0; m < 81; m++) {
            float tv[6];
#pragma unroll
            for (int j = 0; j < 6; j++) tv[j] = Tsh[m * 84 + n0 + j];
#pragma unroll
            for (int i = 0; i < 4; i++) {
                float av = ash[(s0 + i) * 84 + m];
#pragma unroll
                for (int j = 0; j < 6; j++) e[i][j] = fmaf(av, tv[j], e[i][j]);
            }
        }
#pragma unroll
        for (int i = 0; i < 4; i++) {
            float q = 0.f;
#pragma unroll
            for (int j = 0; j < 6; j++) q += e[i][j] * bsh[(s0 + i) * 84 + n0 + j];
            qps[(s0 + i) * 16 + ng] = q;
        }
    }
    __syncthreads();
    if (t < 64) {
        float q = 0.f;
#pragma unroll
        for (int k = 0; k < 14; k++) q += qps[t * 16 + k];
        qvs[t] = q * (1.0f / 256.0f);
    }
    __syncthreads();
    for (int i = t; i < 640; i += 256) {
        int s = i / 10, c = i % 10;
        out[(blockIdx.x * 64 + s) * 10 + c] = qvs[s] * out_w[c] + out_b[c];
    }
}

// ---------------- launch ----------------
extern "C" void kernel_launch(void* const* d_in, const int* in_sizes, int n_in,
                              void* d_out, int out_size) {
    const float* x     = (const float*)d_in[0];
    const float* fcw   = (const float*)d_in[1];
    const float* fcb   = (const float*)d_in[2];
    const float* conv  = (const float*)d_in[3];
    const float* pool  = (const float*)d_in[4];
    const float* last  = (const float*)d_in[5];
    const float* out_w = (const float*)d_in[6];
    const float* out_b = (const float*)d_in[7];
    float* out = (float*)d_out;

    cudaFuncSetAttribute(feats_kernel, cudaFuncAttributeMaxDynamicSharedMemorySize, 8 * 3072 * 4);
    cudaFuncSetAttribute(pauli_kernel, cudaFuncAttributeMaxDynamicSharedMemorySize, 49152 * 4);
    cudaFuncSetAttribute(logits_kernel, cudaFuncAttributeMaxDynamicSharedMemorySize, 18644 * 4);

    gates_kernel<<<1, 32>>>(conv, pool, last);
    feats_kernel<<<256, 256, 8 * 3072 * 4>>>(x, fcw, fcb);
    circuit_kernel<<<256, 64>>>();
    msyrk_kernel<<<dim3(16, 16), 256>>>();
    pauli_kernel<<<1, 1024, 49152 * 4>>>();
    logits_kernel<<<128, 256, 18644 * 4>>>(out_w, out_b, out);
}

// round 5
// speedup vs baseline: 1.3900x; 1.3900x over previous
#include <cuda_runtime.h>
#include <math.h>

// ---------------- scratch (device globals, no allocation) ----------------
__device__ float g_feats[8192 * 8];
__device__ float g_C[256 * 256];   // rows 0-127: Re(U[128:256,:]), rows 128-255: Im
__device__ float g_M[256 * 256];
__device__ float g_T[6561];

// ---------------- complex helpers ----------------
__device__ __forceinline__ float2 cmul(float2 a, float2 b) {
    return make_float2(a.x * b.x - a.y * b.y, a.x * b.y + a.y * b.x);
}
__device__ __forceinline__ float2 cadd(float2 a, float2 b) {
    return make_float2(a.x + b.x, a.y + b.y);
}

__constant__ float2 c_P[4][2][2] = {
    { { {1.f,0.f},{0.f,0.f} }, { {0.f,0.f},{1.f,0.f} } },   // I
    { { {0.f,0.f},{1.f,0.f} }, { {1.f,0.f},{0.f,0.f} } },   // X
    { { {0.f,0.f},{0.f,-1.f} }, { {0.f,1.f},{0.f,0.f} } },  // Y
    { { {1.f,0.f},{0.f,0.f} }, { {0.f,0.f},{-1.f,0.f} } },  // Z
};

__constant__ int c_gwa[17] = {0,2,4,6,1,3,5, 1,3,5,7, 0,4,2, 2,6, 0};
__constant__ int c_gwb[17] = {1,3,5,7,2,4,6, 0,2,4,6, 2,6,4, 0,4, 4};

// syrk symmetric tile pairs (bi<=bj) for 4x4 grid of 64x64 tiles
__constant__ int c_bi[10] = {0,0,0,0,1,1,1,2,2,3};
__constant__ int c_bj[10] = {0,1,2,3,1,2,3,2,3,3};

// ---------------- K1: feats = tanh(x @ fc_w^T + fc_b) ----------------
__global__ __launch_bounds__(256) void feats_kernel(const float* __restrict__ x,
                                                    const float* __restrict__ fcw,
                                                    const float* __restrict__ fcb) {
    extern __shared__ float wsh[];  // 96KB
    int tid = threadIdx.x;
    for (int i = tid * 4; i < 8 * 3072; i += 256 * 4)
        *(float4*)&wsh[i] = *(const float4*)&fcw[i];
    __syncthreads();

    int warp = tid >> 5, lane = tid & 31;
    int grp = blockIdx.x * 8 + warp;
    long long row0 = (long long)grp * 4;

    float acc[8][4];
#pragma unroll
    for (int q = 0; q < 8; q++)
#pragma unroll
        for (int r = 0; r < 4; r++) acc[q][r] = 0.f;

#pragma unroll 4
    for (int it = 0; it < 24; it++) {
        int c = (it * 32 + lane) * 4;
        float4 xv[4];
#pragma unroll
        for (int r = 0; r < 4; r++)
            xv[r] = *(const float4*)&x[(row0 + r) * 3072 + c];
#pragma unroll
        for (int q = 0; q < 8; q++) {
            float4 wv = *(const float4*)&wsh[q * 3072 + c];
#pragma unroll
            for (int r = 0; r < 4; r++) {
                acc[q][r] += wv.x * xv[r].x + wv.y * xv[r].y +
                             wv.z * xv[r].z + wv.w * xv[r].w;
            }
        }
    }
#pragma unroll
    for (int q = 0; q < 8; q++) {
#pragma unroll
        for (int r = 0; r < 4; r++) {
            float v = acc[q][r];
            v += __shfl_down_sync(0xffffffffu, v, 16);
            v += __shfl_down_sync(0xffffffffu, v, 8);
            v += __shfl_down_sync(0xffffffffu, v, 4);
            v += __shfl_down_sync(0xffffffffu, v, 2);
            v += __shfl_down_sync(0xffffffffu, v, 1);
            if (lane == 0) g_feats[(row0 + r) * 8 + q] = tanhf(v + fcb[q]);
        }
    }
}

// ---------------- gate construction ----------------
__device__ __forceinline__ void u3g(float th, float ph, float dl, float2 g[2][2]) {
    float st, ct; __sincosf(0.5f * th, &st, &ct);
    float sp, cp; __sincosf(ph, &sp, &cp);
    float sd, cd; __sincosf(dl, &sd, &cd);
    float spd, cpd; __sincosf(ph + dl, &spd, &cpd);
    g[0][0] = make_float2(ct, 0.f);
    g[0][1] = make_float2(-cd * st, -sd * st);
    g[1][0] = make_float2(cp * st, sp * st);
    g[1][1] = make_float2(cpd * ct, spd * ct);
}

__device__ __forceinline__ void zero4(float2 g[4][4]) {
#pragma unroll
    for (int r = 0; r < 4; r++)
#pragma unroll
        for (int c = 0; c < 4; c++) g[r][c] = make_float2(0.f, 0.f);
}

__device__ __forceinline__ void kron22(const float2 A[2][2], const float2 B[2][2],
                                       float2 P[4][4]) {
#pragma unroll
    for (int ra = 0; ra < 2; ra++)
#pragma unroll
        for (int rb = 0; rb < 2; rb++)
#pragma unroll
            for (int ca = 0; ca < 2; ca++)
#pragma unroll
                for (int cb = 0; cb < 2; cb++)
                    P[ra * 2 + rb][ca * 2 + cb] = cmul(A[ra][ca], B[rb][cb]);
}

__device__ __forceinline__ void mm4(const float2 A[4][4], const float2 B[4][4],
                                    float2 C[4][4]) {
#pragma unroll
    for (int i = 0; i < 4; i++)
#pragma unroll
        for (int j = 0; j < 4; j++) {
            float2 s = make_float2(0.f, 0.f);
#pragma unroll
            for (int k = 0; k < 4; k++) s = cadd(s, cmul(A[i][k], B[k][j]));
            C[i][j] = s;
        }
}

__device__ void build_gate(int g, const float* conv, const float* pool,
                           const float* last, float2* out) {
    float2 G[4][4];
    bool is_conv = (g <= 6) || (g >= 11 && g <= 13);
    bool is_pool = (g >= 7 && g <= 10) || (g == 14) || (g == 15);

    if (is_conv) {
        int layer, idx;
        if (g <= 6) { const int ii[7] = {0, 2, 4, 6, 1, 3, 5}; layer = 0; idx = ii[g]; }
        else        { const int ii[3] = {0, 2, 1};             layer = 1; idx = ii[g - 11]; }
        const float* cw = conv + layer * 8 * 15;
        float2 A1[2][2], B1[2][2], A2[2][2], B2[2][2];
        u3g(cw[idx * 15 + 0], cw[idx * 15 + 1], cw[idx * 15 + 2], A1);
        u3g(cw[(idx + 1) * 15 + 3], cw[(idx + 1) * 15 + 4], cw[(idx + 1) * 15 + 5], B1);
        u3g(cw[idx * 15 + 9], cw[idx * 15 + 10], cw[idx * 15 + 11], A2);
        u3g(cw[(idx + 1) * 15 + 12], cw[(idx + 1) * 15 + 13], cw[(idx + 1) * 15 + 14], B2);
        float2 P1[4][4], P2[4][4], T1[4][4], T2[4][4], IS[4][4];
        kron22(A1, B1, P1);
        kron22(A2, B2, P2);
        { // ZZ
            float sn, cs; __sincosf(0.5f * cw[idx * 15 + 6], &sn, &cs);
            zero4(IS);
            IS[0][0] = make_float2(cs, -sn);
            IS[1][1] = make_float2(cs, sn);
            IS[2][2] = make_float2(cs, sn);
            IS[3][3] = make_float2(cs, -sn);
            mm4(IS, P1, T1);
        }
        { // YY
            float sn, cs; __sincosf(0.5f * cw[idx * 15 + 7], &sn, &cs);
            zero4(IS);
            IS[0][0] = IS[1][1] = IS[2][2] = IS[3][3] = make_float2(cs, 0.f);
            IS[0][3] = make_float2(0.f, sn);
            IS[1][2] = make_float2(0.f, -sn);
            IS[2][1] = make_float2(0.f, -sn);
            IS[3][0] = make_float2(0.f, sn);
            mm4(IS, T1, T2);
        }
        { // XX
            float sn, cs; __sincosf(0.5f * cw[idx * 15 + 8], &sn, &cs);
            zero4(IS);
            IS[0][0] = IS[1][1] = IS[2][2] = IS[3][3] = make_float2(cs, 0.f);
            IS[0][3] = IS[1][2] = IS[2][1] = IS[3][0] = make_float2(0.f, -sn);
            mm4(IS, T2, T1);
        }
        mm4(P2, T1, G);
    } else if (is_pool) {
        int layer = (g <= 10) ? 0 : 1;
        int pi = (g <= 10) ? (g - 7) : (g - 14);
        const float* pw = pool + layer * 4 * 3;
        float2 u[2][2];
        u3g(pw[pi * 3 + 0], pw[pi * 3 + 1], pw[pi * 3 + 2], u);
        zero4(G);
        G[0][0] = make_float2(1.f, 0.f);
        G[1][1] = make_float2(1.f, 0.f);
        G[2][2] = u[0][0]; G[2][3] = u[0][1];
        G[3][2] = u[1][0]; G[3][3] = u[1][1];
    } else {
        zero4(G);
#pragma unroll
        for (int i = 0; i < 4; i++) G[i][i] = make_float2(1.f, 0.f);
        for (int kk = 0; kk < 15; kk++) {
            int pa = (kk + 1) >> 2, pb = (kk + 1) & 3;
            float sn, cs; __sincosf(0.5f * last[kk], &sn, &cs);
            float2 Mk[4][4], T1[4][4];
#pragma unroll
            for (int r = 0; r < 4; r++)
#pragma unroll
                for (int c = 0; c < 4; c++) {
                    float2 p2 = cmul(c_P[pa][r >> 1][c >> 1], c_P[pb][r & 1][c & 1]);
                    Mk[r][c] = make_float2((r == c ? cs : 0.f) + sn * p2.y, -sn * p2.x);
                }
            mm4(Mk, G, T1);
#pragma unroll
            for (int r = 0; r < 4; r++)
#pragma unroll
                for (int c = 0; c < 4; c++) G[r][c] = T1[r][c];
        }
    }
#pragma unroll
    for (int r = 0; r < 4; r++)
#pragma unroll
        for (int c = 0; c < 4; c++) out[r * 4 + c] = G[r][c];
}

// ---------------- K2: apply 17 fused gates; store bottom-half of U ----------------
__device__ __forceinline__ void apply2(float2* s, const float2 g[4][4], int wa, int wb, int t) {
    __syncthreads();
    int ma = 1 << (7 - wa), mb = 1 << (7 - wb);
    int lo = ma < mb ? ma : mb;
    int hi = ma < mb ? mb : ma;
    int k = t;
    k = ((k & ~(lo - 1)) << 1) | (k & (lo - 1));
    k = ((k & ~(hi - 1)) << 1) | (k & (hi - 1));
    int i0 = k, i1 = k | mb, i2 = k | ma, i3 = k | ma | mb;
    float2 v0 = s[i0], v1 = s[i1], v2 = s[i2], v3 = s[i3];
    float2 o0 = cadd(cadd(cmul(g[0][0], v0), cmul(g[0][1], v1)),
                     cadd(cmul(g[0][2], v2), cmul(g[0][3], v3)));
    float2 o1 = cadd(cadd(cmul(g[1][0], v0), cmul(g[1][1], v1)),
                     cadd(cmul(g[1][2], v2), cmul(g[1][3], v3)));
    float2 o2 = cadd(cadd(cmul(g[2][0], v0), cmul(g[2][1], v1)),
                     cadd(cmul(g[2][2], v2), cmul(g[2][3], v3)));
    float2 o3 = cadd(cadd(cmul(g[3][0], v0), cmul(g[3][1], v1)),
                     cadd(cmul(g[3][2], v2), cmul(g[3][3], v3)));
    s[i0] = o0; s[i1] = o1; s[i2] = o2; s[i3] = o3;
}

__global__ __launch_bounds__(64) void circuit_kernel(const float* __restrict__ conv,
                                                     const float* __restrict__ pool,
                                                     const float* __restrict__ last) {
    __shared__ float2 Gsh[17][16];
    __shared__ float2 s[256];
    int t = threadIdx.x;
    if (t < 17) build_gate(t, conv, pool, last, &Gsh[t][0]);
    int col = blockIdx.x;
    for (int k = t; k < 256; k += 64)
        s[k] = make_float2(k == col ? 1.f : 0.f, 0.f);
    __syncthreads();

    for (int g = 0; g < 17; g++) {
        float2 g4[4][4];
#pragma unroll
        for (int r = 0; r < 4; r++)
#pragma unroll
            for (int c = 0; c < 4; c++) g4[r][c] = Gsh[g][r * 4 + c];
        apply2(s, g4, c_gwa[g], c_gwb[g], t);
    }
    __syncthreads();
    // store only rows 128..255 (bit7 = 1): C = [Re; Im]
    for (int k = t; k < 128; k += 64) {
        g_C[k * 256 + col]         = s[k + 128].x;
        g_C[(k + 128) * 256 + col] = s[k + 128].y;
    }
}

// ---------------- K3: M = I - 2 C^T C (symmetric, 64x64 tiles, 4x4/thread) --------
__global__ __launch_bounds__(256) void msyrk_kernel() {
    int bi = c_bi[blockIdx.x] * 64, bj = c_bj[blockIdx.x] * 64;
    __shared__ float As[16][64], Bs[16][64];
    int tx = threadIdx.x & 15, ty = threadIdx.x >> 4;
    float acc[4][4];
#pragma unroll
    for (int i = 0; i < 4; i++)
#pragma unroll
        for (int j = 0; j < 4; j++) acc[i][j] = 0.f;

    for (int k0 = 0; k0 < 256; k0 += 16) {
        for (int idx = threadIdx.x; idx < 1024; idx += 256) {
            int r = idx >> 6, c = idx & 63;
            As[r][c] = g_C[(k0 + r) * 256 + bi + c];
            Bs[r][c] = g_C[(k0 + r) * 256 + bj + c];
        }
        __syncthreads();
#pragma unroll
        for (int kk = 0; kk < 16; kk++) {
            float a[4], b[4];
#pragma unroll
            for (int i = 0; i < 4; i++) a[i] = As[kk][ty * 4 + i];
#pragma unroll
            for (int j = 0; j < 4; j++) b[j] = Bs[kk][tx * 4 + j];
#pragma unroll
            for (int i = 0; i < 4; i++)
#pragma unroll
                for (int j = 0; j < 4; j++) acc[i][j] = fmaf(a[i], b[j], acc[i][j]);
        }
        __syncthreads();
    }
#pragma unroll
    for (int i = 0; i < 4; i++)
#pragma unroll
        for (int j = 0; j < 4; j++) {
            int gi = bi + ty * 4 + i, gj = bj + tx * 4 + j;
            float v = (gi == gj ? 1.f : 0.f) - 2.f * acc[i][j];
            g_M[gi * 256 + gj] = v;
            if (bi != bj) g_M[gj * 256 + gi] = v;
        }
}

// ---------------- K4: M -> T. 9 blocks: digits (p0,p1) fused from gmem ----------
__device__ __forceinline__ void pdec(int p, int* r, int* c, float* sg) {
    if (p == 2) { r[0] = 0; c[0] = 1; r[1] = 1; c[1] = 0; sg[0] = 1.f; sg[1] = 1.f; }
    else        { r[0] = 0; c[0] = 0; r[1] = 1; c[1] = 1; sg[0] = 1.f; sg[1] = (p == 0 ? 1.f : -1.f); }
}

__global__ __launch_bounds__(256) void pauli_kernel() {
    __shared__ float S[4096];
    int t = threadIdx.x;
    int p0 = blockIdx.x / 3, p1 = blockIdx.x % 3;
    int r0[2], c0[2], r1[2], c1[2];
    float s0[2], s1[2];
    pdec(p0, r0, c0, s0);
    pdec(p1, r1, c1, s1);

    // fused digits 0 (offset 128) and 1 (offset 64): 64x64 output, 4 reads each
    for (int o = t; o < 4096; o += 256) {
        int i = o >> 6, j = o & 63;
        float v = 0.f;
#pragma unroll
        for (int t0 = 0; t0 < 2; t0++)
#pragma unroll
            for (int t1 = 0; t1 < 2; t1++)
                v += s0[t0] * s1[t1] *
                     g_M[(i + 128 * r0[t0] + 64 * r1[t1]) * 256 +
                         (j + 128 * c0[t0] + 64 * c1[t1])];
        S[o] = v;
    }
    __syncthreads();

    int nc = 1;
    for (int d = 2; d < 8; d++) {
        int sh = 7 - d;
        int half = 1 << sh;
        int hh = half * half;
        int n_out = nc * 3 * hh;
        int in_blk = 4 * hh;
        int full = half << 1;
        float reg[12];
#pragma unroll
        for (int u = 0; u < 12; u++) {
            int o = t + (u << 8);
            if (o < n_out) {
                int j = o & (half - 1);
                int rr = o >> sh;
                int i = rr & (half - 1);
                int r2 = rr >> sh;
                int p = r2 % 3;
                int c = r2 / 3;
                const float* base = S + c * in_blk;
                float v;
                if (p == 0)      v = base[i * full + j] + base[(i + half) * full + j + half];
                else if (p == 1) v = base[i * full + j] - base[(i + half) * full + j + half];
                else             v = base[i * full + j + half] + base[(i + half) * full + j];
                reg[u] = v;
            }
        }
        __syncthreads();
#pragma unroll
        for (int u = 0; u < 12; u++) {
            int o = t + (u << 8);
            if (o < n_out) S[o] = reg[u];
        }
        __syncthreads();
        nc *= 3;
    }
    for (int o = t; o < 729; o += 256)
        g_T[blockIdx.x * 729 + o] = S[o];
}

// ---------------- K5: qval = a^T T b / 256; logits ----------------
__device__ __forceinline__ float selt(int d, float c, float s) {
    return d == 0 ? 1.f : (d == 1 ? c : s);
}

__global__ __launch_bounds__(256) void logits_kernel(const float* __restrict__ out_w,
                                                     const float* __restrict__ out_b,
                                                     float* __restrict__ out) {
    extern __shared__ float sm[];
    float* Tsh = sm;                 // 81*84
    float* ash = Tsh + 81 * 84;      // 64*84
    float* bsh = ash + 64 * 84;      // 64*84
    float* qps = bsh + 64 * 84;      // 64*16
    float* qvs = qps + 64 * 16;      // 64

    int t = threadIdx.x;
    for (int i = t; i < 81 * 84; i += 256) Tsh[i] = 0.f;
    for (int i = t; i < 64 * 84; i += 256) bsh[i] = 0.f;
    __syncthreads();
    for (int i = t; i < 6561; i += 256) Tsh[(i / 81) * 84 + (i % 81)] = g_T[i];

    {
        int s = t >> 2, part = t & 3;
        int sg = blockIdx.x * 64 + s;
        float tc[8], ts[8];
#pragma unroll
        for (int w = 0; w < 8; w++) {
            float f = g_feats[sg * 8 + w];
            __sincosf(f, &ts[w], &tc[w]);
        }
        int m0 = part * 21;
        int m1 = m0 + 21; if (m1 > 81) m1 = 81;
        for (int m = m0; m < m1; m++) {
            int d0 = m / 27, d1 = (m / 9) % 3, d2 = (m / 3) % 3, d3 = m % 3;
            ash[s * 84 + m] = selt(d0, tc[0], ts[0]) * selt(d1, tc[1], ts[1]) *
                              selt(d2, tc[2], ts[2]) * selt(d3, tc[3], ts[3]);
            bsh[s * 84 + m] = selt(d0, tc[4], ts[4]) * selt(d1, tc[5], ts[5]) *
                              selt(d2, tc[6], ts[6]) * selt(d3, tc[7], ts[7]);
        }
    }
    __syncthreads();

    if (t < 224) {
        int sg = t / 14, ng = t % 14;
        int s0 = sg * 4, n0 = ng * 6;
        float e[4][6];
#pragma unroll
        for (int i = 0; i < 4; i++)
#pragma unroll
            for (int j = 0; j < 6; j++) e[i][j] = 0.f;
        for (int m = 0; m < 81; m++) {
            float tv[6];
#pragma unroll
            for (int j = 0; j < 6; j++) tv[j] = Tsh[m * 84 + n0 + j];
#pragma unroll
            for (int i = 0; i < 4; i++) {
                float av = ash[(s0 + i) * 84 + m];
#pragma unroll
                for (int j = 0; j < 6; j++) e[i][j] = fmaf(av, tv[j], e[i][j]);
            }
        }
#pragma unroll
        for (int i = 0; i < 4; i++) {
            float q = 0.f;
#pragma unroll
            for (int j = 0; j < 6; j++) q += e[i][j] * bsh[(s0 + i) * 84 + n0 + j];
            qps[(s0 + i) * 16 + ng] = q;
        }
    }
    __syncthreads();
    if (t < 64) {
        float q = 0.f;
#pragma unroll
        for (int k = 0; k < 14; k++) q += qps[t * 16 + k];
        qvs[t] = q * (1.0f / 256.0f);
    }
    __syncthreads();
    for (int i = t; i < 640; i += 256) {
        int s = i / 10, c = i % 10;
        out[(blockIdx.x * 64 + s) * 10 + c] = qvs[s] * out_w[c] + out_b[c];
    }
}

// ---------------- launch (fork/join: chain overlaps feats) ----------------
extern "C" void kernel_launch(void* const* d_in, const int* in_sizes, int n_in,
                              void* d_out, int out_size) {
    const float* x     = (const float*)d_in[0];
    const float* fcw   = (const float*)d_in[1];
    const float* fcb   = (const float*)d_in[2];
    const float* conv  = (const float*)d_in[3];
    const float* pool  = (const float*)d_in[4];
    const float* last  = (const float*)d_in[5];
    const float* out_w = (const float*)d_in[6];
    const float* out_b = (const float*)d_in[7];
    float* out = (float*)d_out;

    static cudaStream_t s2 = nullptr;
    static cudaEvent_t ev_fork = nullptr, ev_join = nullptr;
    static bool inited = false;
    if (!inited) {
        cudaStreamCreateWithFlags(&s2, cudaStreamNonBlocking);
        cudaEventCreateWithFlags(&ev_fork, cudaEventDisableTiming);
        cudaEventCreateWithFlags(&ev_join, cudaEventDisableTiming);
        cudaFuncSetAttribute(feats_kernel, cudaFuncAttributeMaxDynamicSharedMemorySize, 8 * 3072 * 4);
        cudaFuncSetAttribute(logits_kernel, cudaFuncAttributeMaxDynamicSharedMemorySize, 18644 * 4);
        inited = true;
    }

    // fork: batch-independent chain on s2
    cudaEventRecord(ev_fork, 0);
    cudaStreamWaitEvent(s2, ev_fork, 0);
    circuit_kernel<<<256, 64, 0, s2>>>(conv, pool, last);
    msyrk_kernel<<<10, 256, 0, s2>>>();
    pauli_kernel<<<9, 256, 0, s2>>>();
    cudaEventRecord(ev_join, s2);

    // main stream: feats (HBM-bound) overlaps the chain
    feats_kernel<<<256, 256, 8 * 3072 * 4>>>(x, fcw, fcb);

    // join, then logits
    cudaStreamWaitEvent(0, ev_join, 0);
    logits_kernel<<<128, 256, 18644 * 4>>>(out_w, out_b, out);
}

// round 8
// speedup vs baseline: 1.4301x; 1.0289x over previous
#include <cuda_runtime.h>
#include <math.h>

// ---------------- scratch (device globals, no allocation) ----------------
__device__ float g_feats[8192 * 8];
__device__ float g_C[256 * 256];   // rows 0-127: Re(U[128:256,:]), rows 128-255: Im
__device__ float g_M[256 * 256];
__device__ float g_T[6561];
__device__ float2 g_G[17][16];

// ---------------- complex helpers ----------------
__device__ __forceinline__ float2 cmul(float2 a, float2 b) {
    return make_float2(a.x * b.x - a.y * b.y, a.x * b.y + a.y * b.x);
}
__device__ __forceinline__ float2 cadd(float2 a, float2 b) {
    return make_float2(a.x + b.x, a.y + b.y);
}

__constant__ float2 c_P[4][2][2] = {
    { { {1.f,0.f},{0.f,0.f} }, { {0.f,0.f},{1.f,0.f} } },   // I
    { { {0.f,0.f},{1.f,0.f} }, { {1.f,0.f},{0.f,0.f} } },   // X
    { { {0.f,0.f},{0.f,-1.f} }, { {0.f,1.f},{0.f,0.f} } },  // Y
    { { {1.f,0.f},{0.f,0.f} }, { {0.f,0.f},{-1.f,0.f} } },  // Z
};

__constant__ int c_gwa[17] = {0,2,4,6,1,3,5, 1,3,5,7, 0,4,2, 2,6, 0};
__constant__ int c_gwb[17] = {1,3,5,7,2,4,6, 0,2,4,6, 2,6,4, 0,4, 4};

// ---------------- K1: feats = tanh(x @ fc_w^T + fc_b) ----------------
// 256 blocks x 512 threads, 2 rows/warp (32 rows/block), 96KB smem,
// 2 blocks/SM -> 32 warps/SM.
__global__ __launch_bounds__(512, 2) void feats_kernel(const float* __restrict__ x,
                                                       const float* __restrict__ fcw,
                                                       const float* __restrict__ fcb) {
    extern __shared__ float wsh[];  // 8*3072 floats = 96KB
    int tid = threadIdx.x;
    for (int i = tid * 4; i < 8 * 3072; i += 512 * 4)
        *(float4*)&wsh[i] = *(const float4*)&fcw[i];
    __syncthreads();

    int warp = tid >> 5, lane = tid & 31;
    long long row0 = ((long long)blockIdx.x * 16 + warp) * 2;  // 0..8190

    float acc[8][2];
#pragma unroll
    for (int q = 0; q < 8; q++) { acc[q][0] = 0.f; acc[q][1] = 0.f; }

#pragma unroll 4
    for (int it = 0; it < 24; it++) {
        int c = (it * 32 + lane) * 4;
        float4 xv0 = *(const float4*)&x[row0 * 3072 + c];
        float4 xv1 = *(const float4*)&x[(row0 + 1) * 3072 + c];
#pragma unroll
        for (int q = 0; q < 8; q++) {
            float4 wv = *(const float4*)&wsh[q * 3072 + c];
            acc[q][0] += wv.x * xv0.x + wv.y * xv0.y + wv.z * xv0.z + wv.w * xv0.w;
            acc[q][1] += wv.x * xv1.x + wv.y * xv1.y + wv.z * xv1.z + wv.w * xv1.w;
        }
    }
#pragma unroll
    for (int q = 0; q < 8; q++) {
#pragma unroll
        for (int r = 0; r < 2; r++) {
            float v = acc[q][r];
            v += __shfl_down_sync(0xffffffffu, v, 16);
            v += __shfl_down_sync(0xffffffffu, v, 8);
            v += __shfl_down_sync(0xffffffffu, v, 4);
            v += __shfl_down_sync(0xffffffffu, v, 2);
            v += __shfl_down_sync(0xffffffffu, v, 1);
            if (lane == 0) g_feats[(row0 + r) * 8 + q] = tanhf(v + fcb[q]);
        }
    }
}

// ---------------- gate construction ----------------
__device__ __forceinline__ void u3g(float th, float ph, float dl, float2 g[2][2]) {
    float st, ct; __sincosf(0.5f * th, &st, &ct);
    float sp, cp; __sincosf(ph, &sp, &cp);
    float sd, cd; __sincosf(dl, &sd, &cd);
    float spd, cpd; __sincosf(ph + dl, &spd, &cpd);
    g[0][0] = make_float2(ct, 0.f);
    g[0][1] = make_float2(-cd * st, -sd * st);
    g[1][0] = make_float2(cp * st, sp * st);
    g[1][1] = make_float2(cpd * ct, spd * ct);
}

__device__ __forceinline__ void zero4(float2 g[4][4]) {
#pragma unroll
    for (int r = 0; r < 4; r++)
#pragma unroll
        for (int c = 0; c < 4; c++) g[r][c] = make_float2(0.f, 0.f);
}

__device__ __forceinline__ void kron22(const float2 A[2][2], const float2 B[2][2],
                                       float2 P[4][4]) {
#pragma unroll
    for (int ra = 0; ra < 2; ra++)
#pragma unroll
        for (int rb = 0; rb < 2; rb++)
#pragma unroll
            for (int ca = 0; ca < 2; ca++)
#pragma unroll
                for (int cb = 0; cb < 2; cb++)
                    P[ra * 2 + rb][ca * 2 + cb] = cmul(A[ra][ca], B[rb][cb]);
}

__device__ __forceinline__ void mm4(const float2 A[4][4], const float2 B[4][4],
                                    float2 C[4][4]) {
#pragma unroll
    for (int i = 0; i < 4; i++)
#pragma unroll
        for (int j = 0; j < 4; j++) {
            float2 s = make_float2(0.f, 0.f);
#pragma unroll
            for (int k = 0; k < 4; k++) s = cadd(s, cmul(A[i][k], B[k][j]));
            C[i][j] = s;
        }
}

__global__ __launch_bounds__(32) void gates_kernel(const float* __restrict__ conv,
                                                   const float* __restrict__ pool,
                                                   const float* __restrict__ last) {
    int g = threadIdx.x;
    if (g >= 17) return;
    float2 G[4][4];
    bool is_conv = (g <= 6) || (g >= 11 && g <= 13);
    bool is_pool = (g >= 7 && g <= 10) || (g == 14) || (g == 15);

    if (is_conv) {
        int layer, idx;
        if (g <= 6) { const int ii[7] = {0, 2, 4, 6, 1, 3, 5}; layer = 0; idx = ii[g]; }
        else        { const int ii[3] = {0, 2, 1};             layer = 1; idx = ii[g - 11]; }
        const float* cw = conv + layer * 8 * 15;
        float2 A1[2][2], B1[2][2], A2[2][2], B2[2][2];
        u3g(cw[idx * 15 + 0], cw[idx * 15 + 1], cw[idx * 15 + 2], A1);
        u3g(cw[(idx + 1) * 15 + 3], cw[(idx + 1) * 15 + 4], cw[(idx + 1) * 15 + 5], B1);
        u3g(cw[idx * 15 + 9], cw[idx * 15 + 10], cw[idx * 15 + 11], A2);
        u3g(cw[(idx + 1) * 15 + 12], cw[(idx + 1) * 15 + 13], cw[(idx + 1) * 15 + 14], B2);
        float2 P1[4][4], P2[4][4], T1[4][4], T2[4][4], IS[4][4];
        kron22(A1, B1, P1);
        kron22(A2, B2, P2);
        { // ZZ
            float sn, cs; __sincosf(0.5f * cw[idx * 15 + 6], &sn, &cs);
            zero4(IS);
            IS[0][0] = make_float2(cs, -sn);
            IS[1][1] = make_float2(cs, sn);
            IS[2][2] = make_float2(cs, sn);
            IS[3][3] = make_float2(cs, -sn);
            mm4(IS, P1, T1);
        }
        { // YY
            float sn, cs; __sincosf(0.5f * cw[idx * 15 + 7], &sn, &cs);
            zero4(IS);
            IS[0][0] = IS[1][1] = IS[2][2] = IS[3][3] = make_float2(cs, 0.f);
            IS[0][3] = make_float2(0.f, sn);
            IS[1][2] = make_float2(0.f, -sn);
            IS[2][1] = make_float2(0.f, -sn);
            IS[3][0] = make_float2(0.f, sn);
            mm4(IS, T1, T2);
        }
        { // XX
            float sn, cs; __sincosf(0.5f * cw[idx * 15 + 8], &sn, &cs);
            zero4(IS);
            IS[0][0] = IS[1][1] = IS[2][2] = IS[3][3] = make_float2(cs, 0.f);
            IS[0][3] = IS[1][2] = IS[2][1] = IS[3][0] = make_float2(0.f, -sn);
            mm4(IS, T2, T1);
        }
        mm4(P2, T1, G);
    } else if (is_pool) {
        int layer = (g <= 10) ? 0 : 1;
        int pi = (g <= 10) ? (g - 7) : (g - 14);
        const float* pw = pool + layer * 4 * 3;
        float2 u[2][2];
        u3g(pw[pi * 3 + 0], pw[pi * 3 + 1], pw[pi * 3 + 2], u);
        zero4(G);
        G[0][0] = make_float2(1.f, 0.f);
        G[1][1] = make_float2(1.f, 0.f);
        G[2][2] = u[0][0]; G[2][3] = u[0][1];
        G[3][2] = u[1][0]; G[3][3] = u[1][1];
    } else {
        zero4(G);
#pragma unroll
        for (int i = 0; i < 4; i++) G[i][i] = make_float2(1.f, 0.f);
        for (int kk = 0; kk < 15; kk++) {
            int pa = (kk + 1) >> 2, pb = (kk + 1) & 3;
            float sn, cs; __sincosf(0.5f * last[kk], &sn, &cs);
            float2 Mk[4][4], T1[4][4];
#pragma unroll
            for (int r = 0; r < 4; r++)
#pragma unroll
                for (int c = 0; c < 4; c++) {
                    float2 p2 = cmul(c_P[pa][r >> 1][c >> 1], c_P[pb][r & 1][c & 1]);
                    Mk[r][c] = make_float2((r == c ? cs : 0.f) + sn * p2.y, -sn * p2.x);
                }
            mm4(Mk, G, T1);
#pragma unroll
            for (int r = 0; r < 4; r++)
#pragma unroll
                for (int c = 0; c < 4; c++) G[r][c] = T1[r][c];
        }
    }
#pragma unroll
    for (int r = 0; r < 4; r++)
#pragma unroll
        for (int c = 0; c < 4; c++) g_G[g][r * 4 + c] = G[r][c];
}

// ---------------- K2: apply 17 fused gates; store bottom-half of U ----------------
__device__ __forceinline__ void apply2(float2* s, const float2 g[4][4], int wa, int wb, int t) {
    __syncthreads();
    int ma = 1 << (7 - wa), mb = 1 << (7 - wb);
    int lo = ma < mb ? ma : mb;
    int hi = ma < mb ? mb : ma;
    int k = t;
    k = ((k & ~(lo - 1)) << 1) | (k & (lo - 1));
    k = ((k & ~(hi - 1)) << 1) | (k & (hi - 1));
    int i0 = k, i1 = k | mb, i2 = k | ma, i3 = k | ma | mb;
    float2 v0 = s[i0], v1 = s[i1], v2 = s[i2], v3 = s[i3];
    float2 o0 = cadd(cadd(cmul(g[0][0], v0), cmul(g[0][1], v1)),
                     cadd(cmul(g[0][2], v2), cmul(g[0][3], v3)));
    float2 o1 = cadd(cadd(cmul(g[1][0], v0), cmul(g[1][1], v1)),
                     cadd(cmul(g[1][2], v2), cmul(g[1][3], v3)));
    float2 o2 = cadd(cadd(cmul(g[2][0], v0), cmul(g[2][1], v1)),
                     cadd(cmul(g[2][2], v2), cmul(g[2][3], v3)));
    float2 o3 = cadd(cadd(cmul(g[3][0], v0), cmul(g[3][1], v1)),
                     cadd(cmul(g[3][2], v2), cmul(g[3][3], v3)));
    s[i0] = o0; s[i1] = o1; s[i2] = o2; s[i3] = o3;
}

__global__ __launch_bounds__(64) void circuit_kernel() {
    __shared__ float2 s[256];
    int t = threadIdx.x;
    int col = blockIdx.x;
    for (int k = t; k < 256; k += 64)
        s[k] = make_float2(k == col ? 1.f : 0.f, 0.f);

    for (int g = 0; g < 17; g++) {
        float2 g4[4][4];
        const float2* Gp = &g_G[g][0];
#pragma unroll
        for (int r = 0; r < 4; r++)
#pragma unroll
            for (int c = 0; c < 4; c++) g4[r][c] = Gp[r * 4 + c];
        apply2(s, g4, c_gwa[g], c_gwb[g], t);
    }
    __syncthreads();
    for (int k = t; k < 128; k += 64) {
        g_C[k * 256 + col]         = s[k + 128].x;
        g_C[(k + 128) * 256 + col] = s[k + 128].y;
    }
}

// ---------------- K3: M = I - 2 C^T C (64 blocks, 32x32 tiles, 2x2/thread) --------
__global__ __launch_bounds__(256) void msyrk_kernel() {
    int bi = (blockIdx.x >> 3) * 32, bj = (blockIdx.x & 7) * 32;
    __shared__ float As[32][33], Bs[32][33];
    int tx = threadIdx.x & 15, ty = threadIdx.x >> 4;
    float a00 = 0.f, a01 = 0.f, a10 = 0.f, a11 = 0.f;

    for (int k0 = 0; k0 < 256; k0 += 32) {
        for (int idx = threadIdx.x; idx < 1024; idx += 256) {
            int r = idx >> 5, c = idx & 31;
            As[r][c] = g_C[(k0 + r) * 256 + bi + c];
            Bs[r][c] = g_C[(k0 + r) * 256 + bj + c];
        }
        __syncthreads();
#pragma unroll
        for (int kk = 0; kk < 32; kk++) {
            float a0 = As[kk][ty * 2], a1 = As[kk][ty * 2 + 1];
            float b0 = Bs[kk][tx * 2], b1 = Bs[kk][tx * 2 + 1];
            a00 = fmaf(a0, b0, a00); a01 = fmaf(a0, b1, a01);
            a10 = fmaf(a1, b0, a10); a11 = fmaf(a1, b1, a11);
        }
        __syncthreads();
    }
    int gi = bi + ty * 2, gj = bj + tx * 2;
    g_M[gi * 256 + gj]           = (gi == gj ? 1.f : 0.f) - 2.f * a00;
    g_M[gi * 256 + gj + 1]       = (gi == gj + 1 ? 1.f : 0.f) - 2.f * a01;
    g_M[(gi + 1) * 256 + gj]     = (gi + 1 == gj ? 1.f : 0.f) - 2.f * a10;
    g_M[(gi + 1) * 256 + gj + 1] = (gi == gj ? 1.f : 0.f) - 2.f * a11;
}

// ---------------- K4: M -> T. 9 blocks: digits (p0,p1) fused from gmem ----------
__device__ __forceinline__ void pdec(int p, int* r, int* c, float* sg) {
    if (p == 2) { r[0] = 0; c[0] = 1; r[1] = 1; c[1] = 0; sg[0] = 1.f; sg[1] = 1.f; }
    else        { r[0] = 0; c[0] = 0; r[1] = 1; c[1] = 1; sg[0] = 1.f; sg[1] = (p == 0 ? 1.f : -1.f); }
}

__global__ __launch_bounds__(256) void pauli_kernel() {
    __shared__ float S[4096];
    int t = threadIdx.x;
    int p0 = blockIdx.x / 3, p1 = blockIdx.x % 3;
    int r0[2], c0[2], r1[2], c1[2];
    float s0[2], s1[2];
    pdec(p0, r0, c0, s0);
    pdec(p1, r1, c1, s1);

    for (int o = t; o < 4096; o += 256) {
        int i = o >> 6, j = o & 63;
        float v = 0.f;
#pragma unroll
        for (int t0 = 0; t0 < 2; t0++)
#pragma unroll
            for (int t1 = 0; t1 < 2; t1++)
                v += s0[t0] * s1[t1] *
                     g_M[(i + 128 * r0[t0] + 64 * r1[t1]) * 256 +
                         (j + 128 * c0[t0] + 64 * c1[t1])];
        S[o] = v;
    }
    __syncthreads();

    int nc = 1;
    for (int d = 2; d < 8; d++) {
        int sh = 7 - d;
        int half = 1 << sh;
        int hh = half * half;
        int n_out = nc * 3 * hh;
        int in_blk = 4 * hh;
        int full = half << 1;
        float reg[12];
#pragma unroll
        for (int u = 0; u < 12; u++) {
            int o = t + (u << 8);
            if (o < n_out) {
                int j = o & (half - 1);
                int rr = o >> sh;
                int i = rr & (half - 1);
                int r2 = rr >> sh;
                int p = r2 % 3;
                int c = r2 / 3;
                const float* base = S + c * in_blk;
                float v;
                if (p == 0)      v = base[i * full + j] + base[(i + half) * full + j + half];
                else if (p == 1) v = base[i * full + j] - base[(i + half) * full + j + half];
                else             v = base[i * full + j + half] + base[(i + half) * full + j];
                reg[u] = v;
            }
        }
        __syncthreads();
#pragma unroll
        for (int u = 0; u < 12; u++) {
            int o = t + (u << 8);
            if (o < n_out) S[o] = reg[u];
        }
        __syncthreads();
        nc *= 3;
    }
    for (int o = t; o < 729; o += 256)
        g_T[blockIdx.x * 729 + o] = S[o];
}

// ---------------- K5: qval = a^T T b / 256; logits ----------------
__device__ __forceinline__ float selt(int d, float c, float s) {
    return d == 0 ? 1.f : (d == 1 ? c : s);
}

__global__ __launch_bounds__(256) void logits_kernel(const float* __restrict__ out_w,
                                                     const float* __restrict__ out_b,
                                                     float* __restrict__ out) {
    extern __shared__ float sm[];
    float* Tsh = sm;                 // 81*84
    float* ash = Tsh + 81 * 84;      // 64*84
    float* bsh = ash + 64 * 84;      // 64*84
    float* qps = bsh + 64 * 84;      // 64*16
    float* qvs = qps + 64 * 16;      // 64

    int t = threadIdx.x;
    for (int i = t; i < 81 * 84; i += 256) Tsh[i] = 0.f;
    for (int i = t; i < 64 * 84; i += 256) bsh[i] = 0.f;
    __syncthreads();
    for (int i = t; i < 6561; i += 256) Tsh[(i / 81) * 84 + (i % 81)] = g_T[i];

    {
        int s = t >> 2, part = t & 3;
        int sg = blockIdx.x * 64 + s;
        float tc[8], ts[8];
#pragma unroll
        for (int w = 0; w < 8; w++) {
            float f = g_feats[sg * 8 + w];
            __sincosf(f, &ts[w], &tc[w]);
        }
        int m0 = part * 21;
        int m1 = m0 + 21; if (m1 > 81) m1 = 81;
        for (int m = m0; m < m1; m++) {
            int d0 = m / 27, d1 = (m / 9) % 3, d2 = (m / 3) % 3, d3 = m % 3;
            ash[s * 84 + m] = selt(d0, tc[0], ts[0]) * selt(d1, tc[1], ts[1]) *
                              selt(d2, tc[2], ts[2]) * selt(d3, tc[3], ts[3]);
            bsh[s * 84 + m] = selt(d0, tc[4], ts[4]) * selt(d1, tc[5], ts[5]) *
                              selt(d2, tc[6], ts[6]) * selt(d3, tc[7], ts[7]);
        }
    }
    __syncthreads();

    if (t < 224) {
        int sg = t / 14, ng = t % 14;
        int s0 = sg * 4, n0 = ng * 6;
        float e[4][6];
#pragma unroll
        for (int i = 0; i < 4; i++)
#pragma unroll
            for (int j = 0; j < 6; j++) e[i][j] = 0.f;
        for (int m = 0; m < 81; m++) {
            float tv[6];
#pragma unroll
            for (int j = 0; j < 6; j++) tv[j] = Tsh[m * 84 + n0 + j];
#pragma unroll
            for (int i = 0; i < 4; i++) {
                float av = ash[(s0 + i) * 84 + m];
#pragma unroll
                for (int j = 0; j < 6; j++) e[i][j] = fmaf(av, tv[j], e[i][j]);
            }
        }
#pragma unroll
        for (int i = 0; i < 4; i++) {
            float q = 0.f;
#pragma unroll
            for (int j = 0; j < 6; j++) q += e[i][j] * bsh[(s0 + i) * 84 + n0 + j];
            qps[(s0 + i) * 16 + ng] = q;
        }
    }
    __syncthreads();
    if (t < 64) {
        float q = 0.f;
#pragma unroll
        for (int k = 0; k < 14; k++) q += qps[t * 16 + k];
        qvs[t] = q * (1.0f / 256.0f);
    }
    __syncthreads();
    for (int i = t; i < 640; i += 256) {
        int s = i / 10, c = i % 10;
        out[(blockIdx.x * 64 + s) * 10 + c] = qvs[s] * out_w[c] + out_b[c];
    }
}

// ---------------- launch (fork/join: chain overlaps feats) ----------------
extern "C" void kernel_launch(void* const* d_in, const int* in_sizes, int n_in,
                              void* d_out, int out_size) {
    const float* x     = (const float*)d_in[0];
    const float* fcw   = (const float*)d_in[1];
    const float* fcb   = (const float*)d_in[2];
    const float* conv  = (const float*)d_in[3];
    const float* pool  = (const float*)d_in[4];
    const float* last  = (const float*)d_in[5];
    const float* out_w = (const float*)d_in[6];
    const float* out_b = (const float*)d_in[7];
    float* out = (float*)d_out;

    static cudaStream_t s2 = nullptr;
    static cudaEvent_t ev_fork = nullptr, ev_join = nullptr;
    static bool inited = false;
    if (!inited) {
        cudaStreamCreateWithFlags(&s2, cudaStreamNonBlocking);
        cudaEventCreateWithFlags(&ev_fork, cudaEventDisableTiming);
        cudaEventCreateWithFlags(&ev_join, cudaEventDisableTiming);
        cudaFuncSetAttribute(feats_kernel, cudaFuncAttributeMaxDynamicSharedMemorySize, 8 * 3072 * 4);
        cudaFuncSetAttribute(logits_kernel, cudaFuncAttributeMaxDynamicSharedMemorySize, 18644 * 4);
        inited = true;
    }

    // fork: batch-independent chain on s2
    cudaEventRecord(ev_fork, 0);
    cudaStreamWaitEvent(s2, ev_fork, 0);
    gates_kernel<<<1, 32, 0, s2>>>(conv, pool, last);
    circuit_kernel<<<256, 64, 0, s2>>>();
    msyrk_kernel<<<64, 256, 0, s2>>>();
    pauli_kernel<<<9, 256, 0, s2>>>();
    cudaEventRecord(ev_join, s2);

    // main stream: feats (HBM-bound) overlaps the chain
    feats_kernel<<<256, 512, 8 * 3072 * 4>>>(x, fcw, fcb);

    // join, then logits
    cudaStreamWaitEvent(0, ev_join, 0);
    logits_kernel<<<128, 256, 18644 * 4>>>(out_w, out_b, out);
}